// round 13
// baseline (speedup 1.0000x reference)
#include <cuda_runtime.h>
#include <math.h>

// ---------------------------------------------------------------------------
// EncoderGRUODE: B=256, T=512, D_IN=64, H=128
// 128 CTAs x 384 threads, warp-specialized:
//   warps 0-7  (256 thr): RK4 stages + W_hh + gate combine. (half = lane>>4,
//               i = 16*wrp + lane&15); half-exchange via shfl_xor(16).
//               Registers: W_node half-row only (64 regs) -> no spills.
//   warps 8-11 (128 thr): out-projection (W_out from L2), out[] store, input
//               staging, i-gate dots (W_ih streamed from L2). Off critical path.
// W_hh (3 gates) in SMEM. All dots use fma.rn.f32x2 (FFMA2). 5 barriers/step.
// ---------------------------------------------------------------------------

#define B_   256
#define T_   512
#define DIN  64
#define H_   128

typedef unsigned long long ull;

// packed weights produced by prep_kernel
__device__ float4 g_whh4[12288];   // [0:4096) R | [4096:8192) Z | [8192:12288) N ; idx=(k/4)*128+i
__device__ float4 g_wih4[6144];    // gate g*2048 + (k/4)*128 + i -> {W_ih[g*128+i][k..k+3]}
__device__ float4 g_wout4[2048];   // (k/4)*64 + j -> {W_out[j][k..k+3]}
__device__ int    g_mask[T_];
__device__ float  g_dt[T_];

// ---------------------------------------------------------------------------
__global__ void prep_kernel(const float* __restrict__ W_hh,
                            const float* __restrict__ W_ih,
                            const float* __restrict__ W_out,
                            const unsigned char* __restrict__ mask_raw,
                            const float* __restrict__ tp)
{
    int gtid = blockIdx.x * blockDim.x + threadIdx.x;
    int nthr = gridDim.x * blockDim.x;

    for (int idx = gtid; idx < 4096; idx += nthr) {
        int kq = idx >> 7, i = idx & 127, k = kq * 4;
        g_whh4[idx] = make_float4(W_hh[i * H_ + k],     W_hh[i * H_ + k + 1],
                                  W_hh[i * H_ + k + 2], W_hh[i * H_ + k + 3]);
        int iz = H_ + i;
        g_whh4[4096 + idx] = make_float4(W_hh[iz * H_ + k],     W_hh[iz * H_ + k + 1],
                                         W_hh[iz * H_ + k + 2], W_hh[iz * H_ + k + 3]);
        int in_ = 2 * H_ + i;
        g_whh4[8192 + idx] = make_float4(W_hh[in_ * H_ + k],     W_hh[in_ * H_ + k + 1],
                                         W_hh[in_ * H_ + k + 2], W_hh[in_ * H_ + k + 3]);
    }
    for (int idx = gtid; idx < 6144; idx += nthr) {
        int g = idx >> 11;
        int rem = idx & 2047;
        int kq = rem >> 7, i = rem & 127, k = kq * 4;
        int row = g * H_ + i;
        g_wih4[idx] = make_float4(W_ih[row * DIN + k],     W_ih[row * DIN + k + 1],
                                  W_ih[row * DIN + k + 2], W_ih[row * DIN + k + 3]);
    }
    for (int idx = gtid; idx < 2048; idx += nthr) {
        int kq = idx >> 6, j = idx & 63, k = kq * 4;
        g_wout4[idx] = make_float4(W_out[j * H_ + k],     W_out[j * H_ + k + 1],
                                   W_out[j * H_ + k + 2], W_out[j * H_ + k + 3]);
    }
    if (gtid < T_)
        g_dt[gtid] = (gtid == 0) ? 0.01f : (tp[gtid] - tp[gtid - 1]);

    // robust mask decode (uint8 / int32 / float32) — unchanged (passed R5-R12)
    if (blockIdx.x == 0 && threadIdx.x == 0) {
        bool nz_nonmult = false, one_mult = false, f32_sig = true;
        for (int i = 0; i < T_; i++) {
            unsigned char v = mask_raw[i];
            int m4 = i & 3;
            if (m4 != 0 && v) nz_nonmult = true;
            if (m4 == 0 && v == 1) one_mult = true;
            if (m4 == 0 || m4 == 1) { if (v != 0) f32_sig = false; }
            else if (m4 == 2)       { if (v != 0 && v != 0x80) f32_sig = false; }
            else                    { if (v != 0 && v != 0x3F) f32_sig = false; }
        }
        if (!nz_nonmult && one_mult) {
            const int* mi = (const int*)mask_raw;
            for (int i = 0; i < T_; i++) g_mask[i] = (mi[i] != 0);
        } else if (nz_nonmult && f32_sig) {
            const float* mf = (const float*)mask_raw;
            for (int i = 0; i < T_; i++) g_mask[i] = (mf[i] != 0.0f);
        } else {
            for (int i = 0; i < T_; i++) g_mask[i] = (mask_raw[i] != 0);
        }
    }
}

// ---------------------------------------------------------------------------
// SMEM layout (float offsets). Row stride 132 on state buffers.
#define RS       132
#define SMF_WHH  0        // 49152 floats (R|Z|N as float4, idx=(k/4)*128+i)
#define SMF_A    49152    // 264: h      [row*RS + k]
#define SMF_B    49416    // 264: RK4 scratch
#define SMF_C    49680    // 264: RK4 scratch
#define SMF_HO   49944    // 264: h_ode
#define SMF_INP  50208    // 136: inp [row*68 + j]
#define SMF_IG   50344    // 768: i-gate results [(gate*2+row)*128 + elem]
#define SMF_TOT  51112
#define SMEM_BYTES (SMF_TOT * 4)   // 204448 B

__device__ __forceinline__ void fma2(ull& acc, ull a, ull b) {
    asm("fma.rn.f32x2 %0, %1, %2, %0;" : "+l"(acc) : "l"(a), "l"(b));
}
__device__ __forceinline__ float psum(ull a) {
    float2 f = *reinterpret_cast<float2*>(&a);
    return f.x + f.y;
}
__device__ __forceinline__ float tanh_fast(float x) {
    float y;
    asm("tanh.approx.f32 %0, %1;" : "=f"(y) : "f"(x));
    return y;
}
__device__ __forceinline__ float sig_fast(float x) {
    return fmaf(0.5f, tanh_fast(0.5f * x), 0.5f);
}

__global__ void __launch_bounds__(384, 1)
enc_gruode_kernel(const float* __restrict__ x,
                  const float* __restrict__ b_ih,
                  const float* __restrict__ b_hh,
                  const float* __restrict__ W_node,
                  const float* __restrict__ b_node,
                  const float* __restrict__ b_out,
                  float* __restrict__ out)
{
    extern __shared__ float sm[];
    const int tid  = threadIdx.x;
    const int lane = tid & 31;
    const int wrp  = tid >> 5;
    const bool rk  = (tid < 256);               // RK4 group?
    const int half = lane >> 4;                 // RK4: k-half AND my row
    const int i    = ((wrp & 7) << 4) | (lane & 15);

    // aux-group identifiers (valid when !rk)
    const int g    = (tid - 256) & 127;         // 0..127
    const int grow = g >> 6, gj = g & 63;       // out-projection row/elem

    // ---- stage packed W_hh into SMEM ----
    {
        float4* d = (float4*)sm;
        for (int idx = tid; idx < 12288; idx += 384) d[idx] = g_whh4[idx];
    }
    for (int idx = tid; idx < 264; idx += 384) sm[SMF_A + idx] = 0.0f;

    // ---- RK4-group register weights: W_node half-row, k-pair packed ----
    ull wn2[32];
    if (rk) {
        const ulonglong2* ws = (const ulonglong2*)(W_node + (size_t)i * H_ + 64 * half);
#pragma unroll
        for (int q = 0; q < 16; q++) { ulonglong2 v = ws[q]; wn2[2*q] = v.x; wn2[2*q+1] = v.y; }
    }

    // combiner constants (RK4 group only; guard OOB for aux)
    const float bn_i = rk ? b_node[i] : 0.0f;
    const float bs_r = rk ? (b_ih[i]       + b_hh[i])       : 0.0f;
    const float bs_z = rk ? (b_ih[128 + i] + b_hh[128 + i]) : 0.0f;
    const float bihn = rk ? b_ih[256 + i] : 0.0f;
    const float bhhn = rk ? b_hh[256 + i] : 0.0f;
    const float bo   = rk ? 0.0f : b_out[gj];

    // aux x / out pointers
    const float* xr   = x   + (size_t)(2 * blockIdx.x + grow) * T_ * DIN + gj;
    float*       orow = out + (size_t)(2 * blockIdx.x + grow) * T_ * DIN + gj;

    __syncthreads();

    float hreg = 0.0f;
    float xv   = rk ? 0.0f : __ldg(xr);          // prefetch x[t=0] (aux)

    // RK4 matvec: full dot for my row via half-dot + shfl_xor(16)
    auto STAGE = [&](const float* buf) -> float {
        const ulonglong2* U = (const ulonglong2*)(buf + 64 * half);
        const ulonglong2* V = (const ulonglong2*)(buf + RS + 64 * half);
        ull a0 = 0, a1 = 0, c0 = 0, c1 = 0;
#pragma unroll
        for (int q = 0; q < 16; q++) {
            ulonglong2 u = U[q], v = V[q];
            fma2(a0, wn2[2*q], u.x); fma2(a1, wn2[2*q+1], u.y);
            fma2(c0, wn2[2*q], v.x); fma2(c1, wn2[2*q+1], v.y);
        }
        float p0 = psum(a0) + psum(a1);
        float p1 = psum(c0) + psum(c1);
        float mine = half ? p1 : p0;
        float oth  = __shfl_xor_sync(0xffffffffu, half ? p0 : p1, 16);
        return mine + oth + bn_i;
    };

    const ulonglong2* WOg  = (const ulonglong2*)g_wout4;   // L2-resident
    const ulonglong2* WIHg = (const ulonglong2*)g_wih4;    // L2-resident

    for (int t = 0; t < T_; ++t) {
        const float dt  = __ldg(g_dt + t);
        const int   msk = __ldg(g_mask + t);
        const float hdt = 0.5f * dt;

        float kv = 0.f, ksum = 0.f, hode = 0.f;

        // ---- P0: RK4 stage1 (A->B) | aux: full outproj(A) -> y, out, INP ----
        if (rk) {
            kv = tanh_fast(STAGE(sm + SMF_A));
            ksum = kv;
            sm[SMF_B + half * RS + i] = fmaf(hdt, kv, hreg);
        } else {
            const ulonglong2* S = (const ulonglong2*)(sm + SMF_A + grow * RS);
            ull o = 0;
#pragma unroll
            for (int q = 0; q < 32; q++) {
                ulonglong2 w = WOg[(size_t)q * 64 + gj];
                ulonglong2 s = S[q];
                fma2(o, w.x, s.x); fma2(o, w.y, s.y);
            }
            float y = psum(o) + bo;              // prev_out = out[t-1]
            if (t) orow[(size_t)(t - 1) * DIN] = y;
            sm[SMF_INP + grow * 68 + gj] = msk ? xv : y;
            if (t + 1 < T_) xv = __ldg(xr + (size_t)(t + 1) * DIN);
        }
        __syncthreads();                                             // B1

        // ---- P1: RK4 stage2 (B->C) | aux: full i-gate dots -> IG ----
        if (rk) {
            kv = tanh_fast(STAGE(sm + SMF_B));
            ksum = fmaf(2.0f, kv, ksum);
            sm[SMF_C + half * RS + i] = fmaf(hdt, kv, hreg);
        } else {
            const ulonglong2* IU = (const ulonglong2*)(sm + SMF_INP);
            const ulonglong2* IV = (const ulonglong2*)(sm + SMF_INP + 68);
            ull ar = 0, az = 0, an = 0, br = 0, bz = 0, bn2 = 0;
#pragma unroll
            for (int q = 0; q < 16; q++) {
                ulonglong2 wr = WIHg[q * 128 + g];
                ulonglong2 wz = WIHg[2048 + q * 128 + g];
                ulonglong2 wn = WIHg[4096 + q * 128 + g];
                ulonglong2 u = IU[q], v = IV[q];
                fma2(ar, wr.x, u.x); fma2(ar, wr.y, u.y);
                fma2(az, wz.x, u.x); fma2(az, wz.y, u.y);
                fma2(an, wn.x, u.x); fma2(an, wn.y, u.y);
                fma2(br, wr.x, v.x); fma2(br, wr.y, v.y);
                fma2(bz, wz.x, v.x); fma2(bz, wz.y, v.y);
                fma2(bn2, wn.x, v.x); fma2(bn2, wn.y, v.y);
            }
            sm[SMF_IG + (0 * 2 + 0) * 128 + g] = psum(ar);
            sm[SMF_IG + (0 * 2 + 1) * 128 + g] = psum(br);
            sm[SMF_IG + (1 * 2 + 0) * 128 + g] = psum(az);
            sm[SMF_IG + (1 * 2 + 1) * 128 + g] = psum(bz);
            sm[SMF_IG + (2 * 2 + 0) * 128 + g] = psum(an);
            sm[SMF_IG + (2 * 2 + 1) * 128 + g] = psum(bn2);
        }
        __syncthreads();                                             // B2

        // ---- P2: RK4 stage3 (C->B) ----
        if (rk) {
            kv = tanh_fast(STAGE(sm + SMF_C));
            ksum = fmaf(2.0f, kv, ksum);
            sm[SMF_B + half * RS + i] = fmaf(dt, kv, hreg);
        }
        __syncthreads();                                             // B3

        // ---- P3: RK4 stage4 (B) -> h_ode ----
        if (rk) {
            kv = tanh_fast(STAGE(sm + SMF_B));
            hode = fmaf(dt * (1.0f / 6.0f), ksum + kv, hreg);
            sm[SMF_HO + half * RS + i] = hode;
        }
        __syncthreads();                                             // B4

        // ---- P4: GRU W_hh dots (SMEM) + gate combine -> h(t), write A ----
        if (rk) {
            const ulonglong2* HU = (const ulonglong2*)(sm + SMF_HO + 64 * half);
            const ulonglong2* HV = (const ulonglong2*)(sm + SMF_HO + RS + 64 * half);
            const ulonglong2* W2 = (const ulonglong2*)sm;
            ull R0 = 0, R1 = 0, Z0 = 0, Z1 = 0, N0 = 0, N1 = 0;
#pragma unroll
            for (int q = 0; q < 16; q++) {
                const int idx = (16 * half + q) * 128 + i;
                ulonglong2 wr = W2[idx];
                ulonglong2 wz = W2[4096 + idx];
                ulonglong2 wn = W2[8192 + idx];
                ulonglong2 u = HU[q], v = HV[q];
                fma2(R0, wr.x, u.x); fma2(R0, wr.y, u.y);
                fma2(R1, wr.x, v.x); fma2(R1, wr.y, v.y);
                fma2(Z0, wz.x, u.x); fma2(Z0, wz.y, u.y);
                fma2(Z1, wz.x, v.x); fma2(Z1, wz.y, v.y);
                fma2(N0, wn.x, u.x); fma2(N0, wn.y, u.y);
                fma2(N1, wn.x, v.x); fma2(N1, wn.y, v.y);
            }
            float r0 = psum(R0), r1 = psum(R1);
            float z0 = psum(Z0), z1 = psum(Z1);
            float n0 = psum(N0), n1 = psum(N1);
            float hrT = (half ? r1 : r0) + __shfl_xor_sync(0xffffffffu, half ? r0 : r1, 16);
            float hzT = (half ? z1 : z0) + __shfl_xor_sync(0xffffffffu, half ? z0 : z1, 16);
            float hnT = (half ? n1 : n0) + __shfl_xor_sync(0xffffffffu, half ? n0 : n1, 16);

            float irT = sm[SMF_IG + (0 * 2 + half) * 128 + i];
            float izT = sm[SMF_IG + (1 * 2 + half) * 128 + i];
            float inT = sm[SMF_IG + (2 * 2 + half) * 128 + i];

            float rr = sig_fast(irT + hrT + bs_r);
            float zz = sig_fast(izT + hzT + bs_z);
            float nn = tanh_fast(inT + bihn + rr * (hnT + bhhn));
            hreg = nn + zz * (hode - nn);
            sm[SMF_A + half * RS + i] = hreg;
        }
        __syncthreads();                                             // B5
    }

    // ---- epilogue: out[T-1] from final A (aux group) ----
    if (!rk) {
        const ulonglong2* S = (const ulonglong2*)(sm + SMF_A + grow * RS);
        ull o = 0;
#pragma unroll
        for (int q = 0; q < 32; q++) {
            ulonglong2 w = WOg[(size_t)q * 64 + gj];
            ulonglong2 s = S[q];
            fma2(o, w.x, s.x); fma2(o, w.y, s.y);
        }
        orow[(size_t)(T_ - 1) * DIN] = psum(o) + bo;
    }
}

// ---------------------------------------------------------------------------
extern "C" void kernel_launch(void* const* d_in, const int* in_sizes, int n_in,
                              void* d_out, int out_size)
{
    const float*         x      = (const float*)d_in[0];
    const float*         tp     = (const float*)d_in[1];
    const unsigned char* mask   = (const unsigned char*)d_in[2];
    const float*         W_ih   = (const float*)d_in[3];
    const float*         W_hh   = (const float*)d_in[4];
    const float*         b_ih   = (const float*)d_in[5];
    const float*         b_hh   = (const float*)d_in[6];
    const float*         W_node = (const float*)d_in[7];
    const float*         b_node = (const float*)d_in[8];
    const float*         W_out  = (const float*)d_in[9];
    const float*         b_out  = (const float*)d_in[10];
    float*               out    = (float*)d_out;

    prep_kernel<<<32, 256>>>(W_hh, W_ih, W_out, mask, tp);

    cudaFuncSetAttribute(enc_gruode_kernel,
                         cudaFuncAttributeMaxDynamicSharedMemorySize,
                         SMEM_BYTES);
    enc_gruode_kernel<<<B_ / 2, 384, SMEM_BYTES>>>(
        x, b_ih, b_hh, W_node, b_node, b_out, out);
}

// round 15
// speedup vs baseline: 1.2768x; 1.2768x over previous
#include <cuda_runtime.h>
#include <cuda_fp16.h>
#include <math.h>

// ---------------------------------------------------------------------------
// EncoderGRUODE: B=256, T=512, D_IN=64, H=128
// 128 CTAs x 256 threads (R12 structure). Thread (half = lane>>4,
// i = 16*wrp + lane&15) owns element i of row `half`, computes k-half `half`
// of every dot. Half-exchange via shfl_xor(16). Dots use fma.rn.f32x2 (FFMA2).
// W_node fp32 regs; W_ih fp16-packed regs (spill fix); W_hh in SMEM;
// W_out streamed from L2. 5 barriers/step; prev_out in register.
// ---------------------------------------------------------------------------

#define B_   256
#define T_   512
#define DIN  64
#define H_   128

typedef unsigned long long ull;

// packed weights produced by prep_kernel
__device__ float4 g_whh4[12288];   // [0:4096) R | [4096:8192) Z | [8192:12288) N ; idx=(k/4)*128+i
__device__ float4 g_wout4[2048];   // (k/4)*64 + j -> {W_out[j][k..k+3]}
__device__ int    g_mask[T_];
__device__ float  g_dt[T_];

// ---------------------------------------------------------------------------
__global__ void prep_kernel(const float* __restrict__ W_hh,
                            const float* __restrict__ W_out,
                            const unsigned char* __restrict__ mask_raw,
                            const float* __restrict__ tp)
{
    int gtid = blockIdx.x * blockDim.x + threadIdx.x;
    int nthr = gridDim.x * blockDim.x;

    for (int idx = gtid; idx < 4096; idx += nthr) {
        int kq = idx >> 7, i = idx & 127, k = kq * 4;
        g_whh4[idx] = make_float4(W_hh[i * H_ + k],     W_hh[i * H_ + k + 1],
                                  W_hh[i * H_ + k + 2], W_hh[i * H_ + k + 3]);
        int iz = H_ + i;
        g_whh4[4096 + idx] = make_float4(W_hh[iz * H_ + k],     W_hh[iz * H_ + k + 1],
                                         W_hh[iz * H_ + k + 2], W_hh[iz * H_ + k + 3]);
        int in_ = 2 * H_ + i;
        g_whh4[8192 + idx] = make_float4(W_hh[in_ * H_ + k],     W_hh[in_ * H_ + k + 1],
                                         W_hh[in_ * H_ + k + 2], W_hh[in_ * H_ + k + 3]);
    }
    for (int idx = gtid; idx < 2048; idx += nthr) {
        int kq = idx >> 6, j = idx & 63, k = kq * 4;
        g_wout4[idx] = make_float4(W_out[j * H_ + k],     W_out[j * H_ + k + 1],
                                   W_out[j * H_ + k + 2], W_out[j * H_ + k + 3]);
    }
    if (gtid < T_)
        g_dt[gtid] = (gtid == 0) ? 0.01f : (tp[gtid] - tp[gtid - 1]);

    // robust mask decode (uint8 / int32 / float32) — unchanged (passed R5-R13)
    if (blockIdx.x == 0 && threadIdx.x == 0) {
        bool nz_nonmult = false, one_mult = false, f32_sig = true;
        for (int i = 0; i < T_; i++) {
            unsigned char v = mask_raw[i];
            int m4 = i & 3;
            if (m4 != 0 && v) nz_nonmult = true;
            if (m4 == 0 && v == 1) one_mult = true;
            if (m4 == 0 || m4 == 1) { if (v != 0) f32_sig = false; }
            else if (m4 == 2)       { if (v != 0 && v != 0x80) f32_sig = false; }
            else                    { if (v != 0 && v != 0x3F) f32_sig = false; }
        }
        if (!nz_nonmult && one_mult) {
            const int* mi = (const int*)mask_raw;
            for (int i = 0; i < T_; i++) g_mask[i] = (mi[i] != 0);
        } else if (nz_nonmult && f32_sig) {
            const float* mf = (const float*)mask_raw;
            for (int i = 0; i < T_; i++) g_mask[i] = (mf[i] != 0.0f);
        } else {
            for (int i = 0; i < T_; i++) g_mask[i] = (mask_raw[i] != 0);
        }
    }
}

// ---------------------------------------------------------------------------
// SMEM layout (float offsets). Row stride 132 on state buffers.
#define RS       132
#define SMF_WHH  0        // 49152 floats (R|Z|N as float4, idx=(k/4)*128+i)
#define SMF_A    49152    // 264: h      [row*RS + k]
#define SMF_B    49416    // 264: RK4 scratch
#define SMF_C    49680    // 264: RK4 scratch
#define SMF_HO   49944    // 264: h_ode
#define SMF_INP  50208    // 136: inp [row*68 + j]
#define SMF_XO   50344    // 512: out-proj partials [row*256 + kq*64 + j]
#define SMF_TOT  50856
#define SMEM_BYTES (SMF_TOT * 4)   // 203424 B

__device__ __forceinline__ void fma2(ull& acc, ull a, ull b) {
    asm("fma.rn.f32x2 %0, %1, %2, %0;" : "+l"(acc) : "l"(a), "l"(b));
}
__device__ __forceinline__ ull f2u(float lo, float hi) {
    ull r;
    asm("mov.b64 %0, {%1, %2};" : "=l"(r) : "f"(lo), "f"(hi));
    return r;
}
__device__ __forceinline__ float psum(ull a) {
    float2 f = *reinterpret_cast<float2*>(&a);
    return f.x + f.y;
}
__device__ __forceinline__ float tanh_fast(float x) {
    float y;
    asm("tanh.approx.f32 %0, %1;" : "=f"(y) : "f"(x));
    return y;
}
__device__ __forceinline__ float sig_fast(float x) {
    return fmaf(0.5f, tanh_fast(0.5f * x), 0.5f);
}

__global__ void __launch_bounds__(256, 1)
enc_gruode_kernel(const float* __restrict__ x,
                  const float* __restrict__ b_ih,
                  const float* __restrict__ b_hh,
                  const float* __restrict__ W_ih,
                  const float* __restrict__ W_node,
                  const float* __restrict__ b_node,
                  const float* __restrict__ b_out,
                  float* __restrict__ out)
{
    extern __shared__ float sm[];
    const int tid  = threadIdx.x;
    const int lane = tid & 31;
    const int wrp  = tid >> 5;
    const int half = lane >> 4;                 // k-half AND my row
    const int i    = (wrp << 4) | (lane & 15);  // my element

    // ---- stage packed W_hh into SMEM ----
    {
        float4* d = (float4*)sm;
        for (int idx = tid; idx < 12288; idx += 256) d[idx] = g_whh4[idx];
    }
    for (int idx = tid; idx < 264; idx += 256) sm[SMF_A + idx] = 0.0f;

    // ---- register weights ----
    ull wn2[32];                     // W_node[i][64*half .. +64), fp32 pairs
    {
        const ulonglong2* ws = (const ulonglong2*)(W_node + (size_t)i * H_ + 64 * half);
#pragma unroll
        for (int q = 0; q < 16; q++) { ulonglong2 v = ws[q]; wn2[2*q] = v.x; wn2[2*q+1] = v.y; }
    }
    // W_ih rows r,z,n over k in [32*half, +32) — fp16-packed (16 half2 per gate)
    __half2 wrh[16], wzh[16], wmh[16];
    {
        const float2* sr = (const float2*)(W_ih + (size_t)i * DIN + 32 * half);
        const float2* sz = (const float2*)(W_ih + (size_t)(H_ + i) * DIN + 32 * half);
        const float2* sn = (const float2*)(W_ih + (size_t)(2 * H_ + i) * DIN + 32 * half);
#pragma unroll
        for (int q = 0; q < 16; q++) {
            float2 a = sr[q]; wrh[q] = __floats2half2_rn(a.x, a.y);
            float2 b = sz[q]; wzh[q] = __floats2half2_rn(b.x, b.y);
            float2 c = sn[q]; wmh[q] = __floats2half2_rn(c.x, c.y);
        }
    }

    // combiner constants (thread is combiner for (row=half, elem=i))
    const float bn_i = b_node[i];
    const float bs_r = b_ih[i]       + b_hh[i];
    const float bs_z = b_ih[128 + i] + b_hh[128 + i];
    const float bihn = b_ih[256 + i];
    const float bhhn = b_hh[256 + i];
    const float bo   = (tid < 128) ? b_out[tid & 63] : 0.0f;

    // x / out pointers for the tid<128 role (row = tid>>6, j = tid&63)
    const float* xr   = x   + (size_t)(2 * blockIdx.x + (tid >> 6)) * T_ * DIN + (tid & 63);
    float*       orow = out + (size_t)(2 * blockIdx.x + (tid >> 6)) * T_ * DIN + (tid & 63);

    __syncthreads();

    float hreg = 0.0f;
    float y    = 0.0f;                            // prev_out kept in register
    float xv   = (tid < 128) ? __ldg(xr) : 0.0f;  // prefetch x[t=0]

    // one RK4 matvec: full dot for my row via half-dot + shfl_xor(16)
    auto STAGE = [&](const float* buf) -> float {
        const ulonglong2* U = (const ulonglong2*)(buf + 64 * half);
        const ulonglong2* V = (const ulonglong2*)(buf + RS + 64 * half);
        ull a0 = 0, a1 = 0, c0 = 0, c1 = 0;
#pragma unroll
        for (int q = 0; q < 16; q++) {
            ulonglong2 u = U[q], v = V[q];
            fma2(a0, wn2[2*q], u.x); fma2(a1, wn2[2*q+1], u.y);
            fma2(c0, wn2[2*q], v.x); fma2(c1, wn2[2*q+1], v.y);
        }
        float p0 = psum(a0) + psum(a1);          // row0 partial, my k-half
        float p1 = psum(c0) + psum(c1);          // row1 partial
        float mine = half ? p1 : p0;
        float oth  = __shfl_xor_sync(0xffffffffu, half ? p0 : p1, 16);
        return mine + oth + bn_i;
    };

    // out-projection partials from buffer A (j = i&63, k-quarter kq, BOTH rows)
    auto OUTPROJ = [&]() {
        const int j = i & 63, kq = (i >> 6) | (half << 1);
        const ulonglong2* S0 = (const ulonglong2*)(sm + SMF_A + 32 * kq);
        const ulonglong2* S1 = (const ulonglong2*)(sm + SMF_A + RS + 32 * kq);
        const ulonglong2* WOg = (const ulonglong2*)g_wout4;
        ull o0 = 0, o1 = 0;
#pragma unroll
        for (int q = 0; q < 8; q++) {
            ulonglong2 w = WOg[(size_t)(8 * kq + q) * 64 + j];
            ulonglong2 s0 = S0[q], s1 = S1[q];
            fma2(o0, w.x, s0.x); fma2(o0, w.y, s0.y);
            fma2(o1, w.x, s1.x); fma2(o1, w.y, s1.y);
        }
        sm[SMF_XO + kq * 64 + j]       = psum(o0);
        sm[SMF_XO + 256 + kq * 64 + j] = psum(o1);
    };

    for (int t = 0; t < T_; ++t) {
        const float dt  = __ldg(g_dt + t);
        const int   msk = __ldg(g_mask + t);
        const float hdt = 0.5f * dt;

        // ---- P0: out-projection of h(t-1) + RK4 stage 1 (both read A) ----
        OUTPROJ();
        float kv = tanh_fast(STAGE(sm + SMF_A));
        float ksum = kv;
        sm[SMF_B + half * RS + i] = fmaf(hdt, kv, hreg);
        __syncthreads();                                             // B1

        // ---- P1: y combine + out store + INP staging ; RK4 stage 2 ----
        if (tid < 128) {
            const int base = SMF_XO + (tid >> 6) * 256 + (tid & 63);
            y = sm[base] + sm[base + 64] + sm[base + 128] + sm[base + 192] + bo;
            if (t) orow[(size_t)(t - 1) * DIN] = y;      // out[t-1]
            sm[SMF_INP + (tid >> 6) * 68 + (tid & 63)] = msk ? xv : y;
            if (t + 1 < T_) xv = __ldg(xr + (size_t)(t + 1) * DIN);
        }
        kv = tanh_fast(STAGE(sm + SMF_B));
        ksum = fmaf(2.0f, kv, ksum);
        sm[SMF_C + half * RS + i] = fmaf(hdt, kv, hreg);
        __syncthreads();                                             // B2

        // ---- P2: i-gate dots (fp16 weights, INP visible) ; RK4 stage 3 ----
        float irT, izT, inT;
        {
            const ulonglong2* IU = (const ulonglong2*)(sm + SMF_INP + 32 * half);
            const ulonglong2* IV = (const ulonglong2*)(sm + SMF_INP + 68 + 32 * half);
            ull ar = 0, az = 0, an = 0, br = 0, bz = 0, bn2 = 0;
#pragma unroll
            for (int q = 0; q < 8; q++) {
                ulonglong2 u = IU[q], v = IV[q];
                float2 wrA = __half22float2(wrh[2*q]);
                float2 wrB = __half22float2(wrh[2*q+1]);
                float2 wzA = __half22float2(wzh[2*q]);
                float2 wzB = __half22float2(wzh[2*q+1]);
                float2 wmA = __half22float2(wmh[2*q]);
                float2 wmB = __half22float2(wmh[2*q+1]);
                ull wra = f2u(wrA.x, wrA.y), wrb = f2u(wrB.x, wrB.y);
                ull wza = f2u(wzA.x, wzA.y), wzb = f2u(wzB.x, wzB.y);
                ull wma = f2u(wmA.x, wmA.y), wmb = f2u(wmB.x, wmB.y);
                fma2(ar, wra, u.x); fma2(ar, wrb, u.y);
                fma2(az, wza, u.x); fma2(az, wzb, u.y);
                fma2(an, wma, u.x); fma2(an, wmb, u.y);
                fma2(br, wra, v.x); fma2(br, wrb, v.y);
                fma2(bz, wza, v.x); fma2(bz, wzb, v.y);
                fma2(bn2, wma, v.x); fma2(bn2, wmb, v.y);
            }
            float r0 = psum(ar), r1 = psum(br);
            float z0 = psum(az), z1 = psum(bz);
            float n0 = psum(an), n1 = psum(bn2);
            irT = (half ? r1 : r0) + __shfl_xor_sync(0xffffffffu, half ? r0 : r1, 16);
            izT = (half ? z1 : z0) + __shfl_xor_sync(0xffffffffu, half ? z0 : z1, 16);
            inT = (half ? n1 : n0) + __shfl_xor_sync(0xffffffffu, half ? n0 : n1, 16);
        }
        kv = tanh_fast(STAGE(sm + SMF_C));
        ksum = fmaf(2.0f, kv, ksum);
        sm[SMF_B + half * RS + i] = fmaf(dt, kv, hreg);
        __syncthreads();                                             // B3

        // ---- P3: RK4 stage 4 -> h_ode ----
        kv = tanh_fast(STAGE(sm + SMF_B));
        const float hode = fmaf(dt * (1.0f / 6.0f), ksum + kv, hreg);
        sm[SMF_HO + half * RS + i] = hode;
        __syncthreads();                                             // B4

        // ---- P4: GRU W_hh dots (SMEM) + gate combine -> h(t), write A ----
        {
            const ulonglong2* HU = (const ulonglong2*)(sm + SMF_HO + 64 * half);
            const ulonglong2* HV = (const ulonglong2*)(sm + SMF_HO + RS + 64 * half);
            const ulonglong2* W2 = (const ulonglong2*)sm;
            ull R0 = 0, R1 = 0, Z0 = 0, Z1 = 0, N0 = 0, N1 = 0;
#pragma unroll
            for (int q = 0; q < 16; q++) {
                const int idx = (16 * half + q) * 128 + i;
                ulonglong2 wr = W2[idx];
                ulonglong2 wz = W2[4096 + idx];
                ulonglong2 wn = W2[8192 + idx];
                ulonglong2 u = HU[q], v = HV[q];
                fma2(R0, wr.x, u.x); fma2(R0, wr.y, u.y);
                fma2(R1, wr.x, v.x); fma2(R1, wr.y, v.y);
                fma2(Z0, wz.x, u.x); fma2(Z0, wz.y, u.y);
                fma2(Z1, wz.x, v.x); fma2(Z1, wz.y, v.y);
                fma2(N0, wn.x, u.x); fma2(N0, wn.y, u.y);
                fma2(N1, wn.x, v.x); fma2(N1, wn.y, v.y);
            }
            float r0 = psum(R0), r1 = psum(R1);
            float z0 = psum(Z0), z1 = psum(Z1);
            float n0 = psum(N0), n1 = psum(N1);
            float hrT = (half ? r1 : r0) + __shfl_xor_sync(0xffffffffu, half ? r0 : r1, 16);
            float hzT = (half ? z1 : z0) + __shfl_xor_sync(0xffffffffu, half ? z0 : z1, 16);
            float hnT = (half ? n1 : n0) + __shfl_xor_sync(0xffffffffu, half ? n0 : n1, 16);

            float rr = sig_fast(irT + hrT + bs_r);
            float zz = sig_fast(izT + hzT + bs_z);
            float nn = tanh_fast(inT + bihn + rr * (hnT + bhhn));
            hreg = nn + zz * (hode - nn);
            sm[SMF_A + half * RS + i] = hreg;
        }
        __syncthreads();                                             // B5
    }

    // ---- epilogue: out[T-1] from final A ----
    OUTPROJ();
    __syncthreads();
    if (tid < 128) {
        const int base = SMF_XO + (tid >> 6) * 256 + (tid & 63);
        float yf = sm[base] + sm[base + 64] + sm[base + 128] + sm[base + 192] + bo;
        orow[(size_t)(T_ - 1) * DIN] = yf;
    }
}

// ---------------------------------------------------------------------------
extern "C" void kernel_launch(void* const* d_in, const int* in_sizes, int n_in,
                              void* d_out, int out_size)
{
    const float*         x      = (const float*)d_in[0];
    const float*         tp     = (const float*)d_in[1];
    const unsigned char* mask   = (const unsigned char*)d_in[2];
    const float*         W_ih   = (const float*)d_in[3];
    const float*         W_hh   = (const float*)d_in[4];
    const float*         b_ih   = (const float*)d_in[5];
    const float*         b_hh   = (const float*)d_in[6];
    const float*         W_node = (const float*)d_in[7];
    const float*         b_node = (const float*)d_in[8];
    const float*         W_out  = (const float*)d_in[9];
    const float*         b_out  = (const float*)d_in[10];
    float*               out    = (float*)d_out;

    prep_kernel<<<32, 256>>>(W_hh, W_out, mask, tp);

    cudaFuncSetAttribute(enc_gruode_kernel,
                         cudaFuncAttributeMaxDynamicSharedMemorySize,
                         SMEM_BYTES);
    enc_gruode_kernel<<<B_ / 2, 256, SMEM_BYTES>>>(
        x, b_ih, b_hh, W_ih, W_node, b_node, b_out, out);
}